// round 1
// baseline (speedup 1.0000x reference)
#include <cuda_runtime.h>

// Block-diagonal irrep linear:
//   out[z, OFF + w*DIM + i] = pw * sum_u W[WOFF + u*MUL + w] * x[z, OFF + u*DIM + i]
// One templated GEMM-ish kernel per irrep block. W and an x Z-tile live in smem.
//
// Thread layout: 256 threads = WLANES (w direction) x ZLANES (batch direction).
// Each thread computes WT w-columns x ZPT batch rows x DIM vector components.

template <int MUL, int DIM, int WLANES, int WT, int ZPT, int OFF, int WOFF>
__global__ void __launch_bounds__(256) irrep_linear_kernel(
    const float* __restrict__ x,
    const float* __restrict__ w,
    float* __restrict__ out,
    int batch, float pw)
{
    constexpr int THREADS = 256;
    constexpr int ZLANES = THREADS / WLANES;
    constexpr int ZTILE  = ZLANES * ZPT;
    constexpr int SEG    = MUL * DIM;     // contiguous floats per row in this block
    static_assert(WLANES * WT == MUL, "w coverage");

    extern __shared__ float smem[];
    float* Ws = smem;               // [MUL][MUL]  (row-major [u][w], as given)
    float* Xs = smem + MUL * MUL;   // [ZTILE][SEG]

    const int tid = threadIdx.x;

    // Stage W (L2-resident; loaded once per CTA, coalesced).
    #pragma unroll 4
    for (int i = tid; i < MUL * MUL; i += THREADS)
        Ws[i] = w[WOFF + i];

    // Stage the x Z-tile (each row segment is contiguous -> coalesced).
    const int z0 = blockIdx.x * ZTILE;
    for (int i = tid; i < ZTILE * SEG; i += THREADS) {
        const int zz = i / SEG;
        const int c  = i - zz * SEG;
        const int z  = z0 + zz;
        Xs[i] = (z < batch) ? x[(long)z * 592 + OFF + c] : 0.0f;
    }
    __syncthreads();

    const int wlane = tid % WLANES;
    const int zlane = tid / WLANES;

    float acc[ZPT][WT][DIM];
    #pragma unroll
    for (int zz = 0; zz < ZPT; ++zz)
        #pragma unroll
        for (int j = 0; j < WT; ++j)
            #pragma unroll
            for (int i2 = 0; i2 < DIM; ++i2)
                acc[zz][j][i2] = 0.0f;

    #pragma unroll 4
    for (int u = 0; u < MUL; ++u) {
        float wv[WT];
        #pragma unroll
        for (int j = 0; j < WT; ++j)
            wv[j] = Ws[u * MUL + wlane + j * WLANES];   // lane-consecutive: conflict-free

        #pragma unroll
        for (int zz = 0; zz < ZPT; ++zz) {
            const float* xr = &Xs[(zlane + zz * ZLANES) * SEG + u * DIM];  // warp-broadcast
            #pragma unroll
            for (int i2 = 0; i2 < DIM; ++i2) {
                const float xv = xr[i2];
                #pragma unroll
                for (int j = 0; j < WT; ++j)
                    acc[zz][j][i2] = fmaf(wv[j], xv, acc[zz][j][i2]);
            }
        }
    }

    // Store. Union of a warp's stores is contiguous per j (lanes cover
    // consecutive w at stride DIM), so sectors are fully utilized.
    #pragma unroll
    for (int zz = 0; zz < ZPT; ++zz) {
        const int z = z0 + zlane + zz * ZLANES;
        if (z < batch) {
            float* orow = out + (long)z * 592 + OFF;
            #pragma unroll
            for (int j = 0; j < WT; ++j) {
                const int wcol = wlane + j * WLANES;
                #pragma unroll
                for (int i2 = 0; i2 < DIM; ++i2)
                    orow[wcol * DIM + i2] = pw * acc[zz][j][i2];
            }
        }
    }
}

extern "C" void kernel_launch(void* const* d_in, const int* in_sizes, int n_in,
                              void* d_out, int out_size)
{
    const float* x = (const float*)d_in[0];
    const float* w = (const float*)d_in[1];
    float* out = (float*)d_out;
    const int batch = in_sizes[0] / 592;

    // ---- block 0: mul=128, dim=1, OFF=0,   WOFF=0      pw=128^-0.5
    {
        constexpr int ZTILE = (256 / 32) * 8;   // 64
        const size_t smem = (size_t)(128 * 128 + ZTILE * 128) * sizeof(float); // 96 KB
        cudaFuncSetAttribute(irrep_linear_kernel<128, 1, 32, 4, 8, 0, 0>,
                             cudaFuncAttributeMaxDynamicSharedMemorySize, (int)smem);
        irrep_linear_kernel<128, 1, 32, 4, 8, 0, 0>
            <<<(batch + ZTILE - 1) / ZTILE, 256, smem>>>(x, w, out, batch, 0.08838834764831845f);
    }
    // ---- block 1: mul=64, dim=3, OFF=128, WOFF=16384  pw=1/8
    {
        constexpr int ZTILE = (256 / 32) * 4;   // 32
        const size_t smem = (size_t)(64 * 64 + ZTILE * 192) * sizeof(float);   // 40 KB
        irrep_linear_kernel<64, 3, 32, 2, 4, 128, 16384>
            <<<(batch + ZTILE - 1) / ZTILE, 256, smem>>>(x, w, out, batch, 0.125f);
    }
    // ---- block 2: mul=32, dim=5, OFF=320, WOFF=20480  pw=32^-0.5
    {
        constexpr int ZTILE = (256 / 32) * 4;   // 32
        const size_t smem = (size_t)(32 * 32 + ZTILE * 160) * sizeof(float);   // 24 KB
        irrep_linear_kernel<32, 5, 32, 1, 4, 320, 20480>
            <<<(batch + ZTILE - 1) / ZTILE, 256, smem>>>(x, w, out, batch, 0.17677669529663687f);
    }
    // ---- block 3: mul=16, dim=7, OFF=480, WOFF=21504  pw=1/4
    {
        constexpr int ZTILE = (256 / 16) * 4;   // 64
        const size_t smem = (size_t)(16 * 16 + ZTILE * 112) * sizeof(float);   // 29 KB
        irrep_linear_kernel<16, 7, 16, 1, 4, 480, 21504>
            <<<(batch + ZTILE - 1) / ZTILE, 256, smem>>>(x, w, out, batch, 0.25f);
    }
}

// round 3
// speedup vs baseline: 1.3490x; 1.3490x over previous
#include <cuda_runtime.h>
#include <cuda_bf16.h>
#include <cstdint>

// ============================================================================
// Block-diagonal irrep linear via mma.sync (HMMA) bf16 3-term split.
// Per block: D[m,n] = sum_k A[m,k]*W[k,n], m = z*DIM + i, M = batch*DIM,
// K = N = MUL. A*W ~= Ah*Wh + Ah*Wl + Al*Wh  (split rel err ~1e-5).
// CTA: 256 thr = 8 warps x m16. N = MUL per warp, K chunked at 64.
// ============================================================================

__device__ __forceinline__ uint32_t smem_u32(const void* p) {
    uint32_t a;
    asm("{ .reg .u64 t; cvta.to.shared.u64 t, %1; cvt.u32.u64 %0, t; }" : "=r"(a) : "l"(p));
    return a;
}
__device__ __forceinline__ void ldsm4(uint32_t* r, uint32_t addr) {
    asm volatile("ldmatrix.sync.aligned.m8n8.x4.shared.b16 {%0,%1,%2,%3}, [%4];"
                 : "=r"(r[0]), "=r"(r[1]), "=r"(r[2]), "=r"(r[3]) : "r"(addr));
}
__device__ __forceinline__ void mma16816(float* c, const uint32_t* a, const uint32_t* b) {
    asm volatile("mma.sync.aligned.m16n8k16.row.col.f32.bf16.bf16.f32 "
                 "{%0,%1,%2,%3}, {%4,%5,%6,%7}, {%8,%9}, {%0,%1,%2,%3};"
                 : "+f"(c[0]), "+f"(c[1]), "+f"(c[2]), "+f"(c[3])
                 : "r"(a[0]), "r"(a[1]), "r"(a[2]), "r"(a[3]), "r"(b[0]), "r"(b[1]));
}
__device__ __forceinline__ void split_bf16(float v, __nv_bfloat16& h, __nv_bfloat16& l) {
    h = __float2bfloat16(v);
    l = __float2bfloat16(v - __bfloat162float(h));
}

// Padded strides: (KC+8) halves -> row stride bytes = 2*KC+16, which is
// congruent to 16B mod 128B for KC in {64,32,16}: ldmatrix conflict-free.

template <int MUL, int DIM, int OFF, int WOFF>
__global__ void __launch_bounds__(256, 2) irrep_hmma_kernel(
    const float* __restrict__ x, const float* __restrict__ w,
    float* __restrict__ out, int batch, float pw)
{
    constexpr int KC = (MUL < 64) ? MUL : 64;      // K per chunk
    constexpr int NCHUNK = MUL / KC;
    constexpr int KS = KC / 16;                    // k16 steps per chunk
    constexpr int NF = MUL / 8;                    // n8 fragments
    constexpr int PA = KC + 8;                     // A row stride (halves)
    constexpr int PB = KC + 8;                     // B row stride (halves)
    constexpr int PD = MUL + 8;                    // Dstage row stride (floats)

    extern __shared__ char smem[];
    __nv_bfloat16* Ah = (__nv_bfloat16*)smem;
    __nv_bfloat16* Al = Ah + 128 * PA;
    __nv_bfloat16* Bh = Al + 128 * PA;
    __nv_bfloat16* Bl = Bh + MUL * PB;
    float* Dst = (float*)smem;                     // epilogue alias

    const int tid  = threadIdx.x;
    const int lane = tid & 31;
    const int wid  = tid >> 5;
    const int m0   = blockIdx.x * 128;
    const int mw   = wid * 16;

    const int z_lo = m0 / DIM;
    int z_hi = (m0 + 127) / DIM;
    if (z_hi > batch - 1) z_hi = batch - 1;
    const int n_rows = z_hi - z_lo + 1;

    // per-lane ldmatrix base addresses
    const uint32_t sAh = smem_u32(Ah), sAl = smem_u32(Al);
    const uint32_t sBh = smem_u32(Bh), sBl = smem_u32(Bl);
    const int a_row = lane & 15;
    const int a_k   = ((lane >> 4) & 1) * 8;
    const uint32_t aoff = (uint32_t)(((mw + a_row) * PA + a_k) * 2);
    const int b_n = (lane & 7) + ((lane >> 4) & 1) * 8;
    const int b_k = ((lane >> 3) & 1) * 8;
    const uint32_t boff = (uint32_t)((b_n * PB + b_k) * 2);

    float acc[NF][4];
    #pragma unroll
    for (int f = 0; f < NF; ++f)
        #pragma unroll
        for (int j = 0; j < 4; ++j) acc[f][j] = 0.0f;

    for (int c = 0; c < NCHUNK; ++c) {
        if (c) __syncthreads();   // protect smem reuse across chunks

        // ---- stage B chunk: w[(c*KC+kl)*MUL + n] -> Bh/Bl[n*PB + kl] ----
        for (int idx = tid; idx < KC * MUL; idx += 256) {
            const int kl = idx / MUL;
            const int n  = idx - kl * MUL;
            __nv_bfloat16 h, l;
            split_bf16(w[WOFF + (c * KC + kl) * MUL + n], h, l);
            Bh[n * PB + kl] = h;
            Bl[n * PB + kl] = l;
        }

        // ---- stage A chunk ----
        const int c0 = OFF + c * KC * DIM;
        if constexpr (DIM == 1) {
            const int nr = (batch - z_lo < 128) ? (batch - z_lo) : 128;
            for (int idx = tid; idx < nr * (KC / 4); idx += 256) {
                const int r = idx / (KC / 4);
                const int q = idx - r * (KC / 4);
                const float4 v = *(const float4*)(x + (long)(z_lo + r) * 592 + c0 + q * 4);
                __nv_bfloat16 h0, h1, h2, h3, l0, l1, l2, l3;
                split_bf16(v.x, h0, l0); split_bf16(v.y, h1, l1);
                split_bf16(v.z, h2, l2); split_bf16(v.w, h3, l3);
                uint2 ph, pl;
                ph.x = ((uint32_t)__bfloat16_as_ushort(h1) << 16) | __bfloat16_as_ushort(h0);
                ph.y = ((uint32_t)__bfloat16_as_ushort(h3) << 16) | __bfloat16_as_ushort(h2);
                pl.x = ((uint32_t)__bfloat16_as_ushort(l1) << 16) | __bfloat16_as_ushort(l0);
                pl.y = ((uint32_t)__bfloat16_as_ushort(l3) << 16) | __bfloat16_as_ushort(l2);
                *(uint2*)&Ah[r * PA + q * 4] = ph;
                *(uint2*)&Al[r * PA + q * 4] = pl;
            }
        } else {
            const int Wc = KC * DIM;
            for (int idx = tid; idx < n_rows * Wc; idx += 256) {
                const int zz = idx / Wc;
                const int cc = idx - zz * Wc;
                const int z  = z_lo + zz;
                const float val = x[(long)z * 592 + c0 + cc];
                const int k = cc / DIM;
                const int i = cc - k * DIM;
                const int ml = z * DIM + i - m0;
                if (ml >= 0 && ml < 128) {
                    __nv_bfloat16 h, l;
                    split_bf16(val, h, l);
                    Ah[ml * PA + k] = h;
                    Al[ml * PA + k] = l;
                }
            }
        }
        __syncthreads();

        // ---- MMA ----
        #pragma unroll
        for (int ks = 0; ks < KS; ++ks) {
            uint32_t ah[4], al[4];
            ldsm4(ah, sAh + aoff + ks * 32);
            ldsm4(al, sAl + aoff + ks * 32);
            #pragma unroll
            for (int nf2 = 0; nf2 < NF / 2; ++nf2) {
                uint32_t bh[4], bl[4];
                const uint32_t bo = boff + (uint32_t)(nf2 * 16 * PB * 2) + ks * 32;
                ldsm4(bh, sBh + bo);
                ldsm4(bl, sBl + bo);
                mma16816(acc[2 * nf2],     ah, bh);
                mma16816(acc[2 * nf2 + 1], ah, bh + 2);
                mma16816(acc[2 * nf2],     ah, bl);
                mma16816(acc[2 * nf2 + 1], ah, bl + 2);
                mma16816(acc[2 * nf2],     al, bh);
                mma16816(acc[2 * nf2 + 1], al, bh + 2);
            }
        }
    }

    // ---- epilogue: regs -> smem transpose stage -> coalesced gmem ----
    __syncthreads();
    {
        const int r0 = mw + lane / 4;
        const int ncol = (lane & 3) * 2;
        #pragma unroll
        for (int nf = 0; nf < NF; ++nf) {
            float2 v0 = make_float2(acc[nf][0] * pw, acc[nf][1] * pw);
            float2 v1 = make_float2(acc[nf][2] * pw, acc[nf][3] * pw);
            *(float2*)&Dst[r0 * PD + nf * 8 + ncol]       = v0;
            *(float2*)&Dst[(r0 + 8) * PD + nf * 8 + ncol] = v1;
        }
    }
    __syncthreads();
    {
        const int Wn = MUL * DIM;
        for (int idx = tid; idx < n_rows * Wn; idx += 256) {
            const int zz = idx / Wn;
            const int cc = idx - zz * Wn;
            const int z  = z_lo + zz;
            const int n  = cc / DIM;
            const int i  = cc - n * DIM;
            const int ml = z * DIM + i - m0;
            if (ml >= 0 && ml < 128)
                out[(long)z * 592 + OFF + cc] = Dst[ml * PD + n];
        }
    }
}

extern "C" void kernel_launch(void* const* d_in, const int* in_sizes, int n_in,
                              void* d_out, int out_size)
{
    const float* x = (const float*)d_in[0];
    const float* w = (const float*)d_in[1];
    float* out = (float*)d_out;
    const int batch = in_sizes[0] / 592;

    // block 0: MUL=128 DIM=1 OFF=0   WOFF=0      pw=128^-0.5
    {
        constexpr int PA = 72, PB = 72;
        const size_t smem = (size_t)(2 * 128 * PA + 2 * 128 * PB) * 2;  // 73728
        cudaFuncSetAttribute(irrep_hmma_kernel<128, 1, 0, 0>,
                             cudaFuncAttributeMaxDynamicSharedMemorySize, (int)smem);
        irrep_hmma_kernel<128, 1, 0, 0>
            <<<(batch + 127) / 128, 256, smem>>>(x, w, out, batch, 0.08838834764831845f);
    }
    // block 1: MUL=64 DIM=3 OFF=128 WOFF=16384  pw=0.125
    {
        constexpr int PA = 72, PB = 72;
        const size_t smem = (size_t)(2 * 128 * PA + 2 * 64 * PB) * 2;   // 55296
        cudaFuncSetAttribute(irrep_hmma_kernel<64, 3, 128, 16384>,
                             cudaFuncAttributeMaxDynamicSharedMemorySize, (int)smem);
        irrep_hmma_kernel<64, 3, 128, 16384>
            <<<(batch * 3 + 127) / 128, 256, smem>>>(x, w, out, batch, 0.125f);
    }
    // block 2: MUL=32 DIM=5 OFF=320 WOFF=20480  pw=32^-0.5
    {
        constexpr int PA = 40, PB = 40;
        const size_t smem = (size_t)(2 * 128 * PA + 2 * 32 * PB) * 2;   // 25600
        irrep_hmma_kernel<32, 5, 320, 20480>
            <<<(batch * 5 + 127) / 128, 256, smem>>>(x, w, out, batch, 0.17677669529663687f);
    }
    // block 3: MUL=16 DIM=7 OFF=480 WOFF=21504  pw=0.25
    {
        constexpr int PA = 24, PB = 24;
        const size_t smem = (size_t)(2 * 128 * PA + 2 * 16 * PB) * 2;   // 13824
        irrep_hmma_kernel<16, 7, 480, 21504>
            <<<(batch * 7 + 127) / 128, 256, smem>>>(x, w, out, batch, 0.25f);
    }
}

// round 4
// speedup vs baseline: 1.8865x; 1.3985x over previous
#include <cuda_runtime.h>
#include <cuda_bf16.h>
#include <cstdint>

// ============================================================================
// Block-diagonal irrep linear, fused HMMA bf16 3-term split kernel.
// Per block: D[m,n] = sum_k A[m,k]*W[k,n]*pw, m = z*DIM+i.
// W pre-split (hi/lo bf16, pw folded, padded smem layout) by a prep kernel.
// ============================================================================

__device__ __forceinline__ uint32_t smem_u32(const void* p) {
    uint32_t a;
    asm("{ .reg .u64 t; cvta.to.shared.u64 t, %1; cvt.u32.u64 %0, t; }" : "=r"(a) : "l"(p));
    return a;
}
__device__ __forceinline__ void ldsm4(uint32_t* r, uint32_t addr) {
    asm volatile("ldmatrix.sync.aligned.m8n8.x4.shared.b16 {%0,%1,%2,%3}, [%4];"
                 : "=r"(r[0]), "=r"(r[1]), "=r"(r[2]), "=r"(r[3]) : "r"(addr));
}
__device__ __forceinline__ void mma16816(float* c, const uint32_t* a, const uint32_t* b) {
    asm volatile("mma.sync.aligned.m16n8k16.row.col.f32.bf16.bf16.f32 "
                 "{%0,%1,%2,%3}, {%4,%5,%6,%7}, {%8,%9}, {%0,%1,%2,%3};"
                 : "+f"(c[0]), "+f"(c[1]), "+f"(c[2]), "+f"(c[3])
                 : "r"(a[0]), "r"(a[1]), "r"(a[2]), "r"(a[3]), "r"(b[0]), "r"(b[1]));
}
__device__ __forceinline__ void split_bf16(float v, __nv_bfloat16& h, __nv_bfloat16& l) {
    h = __float2bfloat16(v);
    l = __float2bfloat16(v - __bfloat162float(h));
}
__device__ __forceinline__ uint32_t pack2(__nv_bfloat16 a, __nv_bfloat16 b) {
    return ((uint32_t)__bfloat16_as_ushort(b) << 16) | __bfloat16_as_ushort(a);
}

// ---- W images: per block, per K-chunk, [n][kl] with padded stride PB=KC+8 ----
// halves offsets: b0=0 (4 chunks x 128x40), b1=20480 (2 x 64x40),
//                 b2=25600 (32x40), b3=26880 (16x24); total 27264
__device__ __align__(16) __nv_bfloat16 g_bh[27264];
__device__ __align__(16) __nv_bfloat16 g_bl[27264];

__global__ void w_prep_kernel(const float* __restrict__ w) {
    int t = blockIdx.x * 256 + threadIdx.x;
    if (t >= 21760) return;
    int dst; float pw;
    if (t < 16384) {                  // block0: MUL=128, KC=32
        int u = t >> 7, n = t & 127;
        dst = ((u >> 5) * 5120) + n * 40 + (u & 31);
        pw = 0.08838834764831845f;
    } else if (t < 20480) {           // block1: MUL=64, KC=32
        int local = t - 16384;
        int u = local >> 6, n = local & 63;
        dst = 20480 + ((u >> 5) * 2560) + n * 40 + (u & 31);
        pw = 0.125f;
    } else if (t < 21504) {           // block2: MUL=32, KC=32
        int local = t - 20480;
        int u = local >> 5, n = local & 31;
        dst = 25600 + n * 40 + u;
        pw = 0.17677669529663687f;
    } else {                          // block3: MUL=16, KC=16
        int local = t - 21504;
        int u = local >> 4, n = local & 15;
        dst = 26880 + n * 24 + u;
        pw = 0.25f;
    }
    float val = w[t] * pw;
    __nv_bfloat16 h, l;
    split_bf16(val, h, l);
    g_bh[dst] = h;
    g_bl[dst] = l;
}

// ---- per-block GEMM body ----
template <int MUL, int DIM, int OFF, int IMG, int MROWS>
__device__ __forceinline__ void irrep_gemm(
    const float* __restrict__ x, float* __restrict__ out,
    int batch, int cta, char* smem)
{
    constexpr int KC  = (MUL < 32) ? MUL : 32;   // K per chunk (pow2)
    constexpr int NCH = MUL / KC;
    constexpr int KS  = KC / 16;
    constexpr int PA  = KC + 8;                   // padded strides (halves)
    constexpr int PB  = KC + 8;
    constexpr int WN  = (MROWS == 64) ? 2 : 1;    // n-warp split (block0 only)
    constexpr int NPW = MUL / WN;                 // n per warp
    constexpr int NF  = NPW / 8;
    constexpr int PD  = MUL + 8;                  // Dstage stride (floats)

    __nv_bfloat16* Ah = (__nv_bfloat16*)smem;
    __nv_bfloat16* Al = Ah + MROWS * PA;
    __nv_bfloat16* Bh = Al + MROWS * PA;
    __nv_bfloat16* Bl = Bh + MUL * PB;
    float* Dst = (float*)smem;                    // epilogue alias

    const int tid  = threadIdx.x;
    const int lane = tid & 31;
    const int wid  = tid >> 5;
    const int m0   = cta * MROWS;
    const int mw   = (wid & (MROWS / 16 - 1)) * 16;
    const int nw   = (WN == 2) ? (wid >> 2) * NPW : 0;

    const int z_lo = m0 / DIM;
    int z_hi = (m0 + MROWS - 1) / DIM;
    if (z_hi > batch - 1) z_hi = batch - 1;
    const int n_rows = z_hi - z_lo + 1;
    const int mbase = z_lo * DIM - m0;            // in (-DIM, 0]

    const uint32_t sAh = smem_u32(Ah), sAl = smem_u32(Al);
    const uint32_t sBh = smem_u32(Bh), sBl = smem_u32(Bl);
    const uint32_t aoff = (uint32_t)(((mw + (lane & 15)) * PA + ((lane >> 4) & 1) * 8) * 2);
    const uint32_t boff = (uint32_t)(((nw + (lane & 7) + ((lane >> 4) & 1) * 8) * PB
                                      + ((lane >> 3) & 1) * 8) * 2);

    float acc[NF][4];
    #pragma unroll
    for (int f = 0; f < NF; ++f)
        #pragma unroll
        for (int j = 0; j < 4; ++j) acc[f][j] = 0.0f;

    for (int c = 0; c < NCH; ++c) {
        if (c) __syncthreads();

        // ---- stage B chunk: plain uint4 copies of prepped images ----
        {
            const uint4* gh = (const uint4*)(g_bh + IMG + c * MUL * PB);
            const uint4* gl = (const uint4*)(g_bl + IMG + c * MUL * PB);
            uint4* dh = (uint4*)Bh;
            uint4* dl = (uint4*)Bl;
            constexpr int CNT = MUL * PB / 8;
            for (int i = tid; i < CNT; i += 256) { dh[i] = gh[i]; dl[i] = gl[i]; }
        }

        // ---- stage A chunk ----
        const int c0 = OFF + c * KC * DIM;
        if constexpr (DIM == 1) {
            const int nr = (batch - z_lo < MROWS) ? (batch - z_lo) : MROWS;
            constexpr int Q = KC / 4;             // float4s per row (pow2)
            for (int idx = tid; idx < nr * Q; idx += 256) {
                const int r = idx / Q;
                const int q = idx & (Q - 1);
                const float4 v = *(const float4*)(x + (long)(z_lo + r) * 592 + c0 + q * 4);
                __nv_bfloat16 h0, l0, h1, l1, h2, l2, h3, l3;
                split_bf16(v.x, h0, l0); split_bf16(v.y, h1, l1);
                split_bf16(v.z, h2, l2); split_bf16(v.w, h3, l3);
                uint2 ph = make_uint2(pack2(h0, h1), pack2(h2, h3));
                uint2 pl = make_uint2(pack2(l0, l1), pack2(l2, l3));
                *(uint2*)&Ah[r * PA + q * 4] = ph;
                *(uint2*)&Al[r * PA + q * 4] = pl;
            }
        } else {
            constexpr int KC2 = KC / 2;           // u-pairs per row (pow2)
            constexpr int ZST = 256 / KC2;
            const int up   = (tid & (KC2 - 1)) * 2;
            const int zoff = tid / KC2;
            for (int zz = zoff; zz < n_rows; zz += ZST) {
                const float* base = x + (long)(z_lo + zz) * 592 + c0 + up * DIM;
                const int mlb = mbase + zz * DIM;
                #pragma unroll
                for (int i = 0; i < DIM; ++i) {
                    const int ml = mlb + i;
                    if (ml >= 0 && ml < MROWS) {
                        const float v0 = base[i];
                        const float v1 = base[i + DIM];
                        __nv_bfloat16 h0, l0, h1, l1;
                        split_bf16(v0, h0, l0); split_bf16(v1, h1, l1);
                        *(uint32_t*)&Ah[ml * PA + up] = pack2(h0, h1);
                        *(uint32_t*)&Al[ml * PA + up] = pack2(l0, l1);
                    }
                }
            }
        }
        __syncthreads();

        // ---- MMA: 3-term split ----
        #pragma unroll
        for (int ks = 0; ks < KS; ++ks) {
            uint32_t ah[4], al[4];
            ldsm4(ah, sAh + aoff + ks * 32);
            ldsm4(al, sAl + aoff + ks * 32);
            #pragma unroll
            for (int nf2 = 0; nf2 < NF / 2; ++nf2) {
                uint32_t bh[4], bl[4];
                const uint32_t bo = boff + (uint32_t)(nf2 * 16 * PB * 2) + ks * 32;
                ldsm4(bh, sBh + bo);
                ldsm4(bl, sBl + bo);
                mma16816(acc[2 * nf2],     ah, bh);
                mma16816(acc[2 * nf2 + 1], ah, bh + 2);
                mma16816(acc[2 * nf2],     ah, bl);
                mma16816(acc[2 * nf2 + 1], ah, bl + 2);
                mma16816(acc[2 * nf2],     al, bh);
                mma16816(acc[2 * nf2 + 1], al, bh + 2);
            }
        }
    }

    // ---- epilogue: regs -> Dstage -> coalesced gmem (pw already folded) ----
    __syncthreads();
    {
        const int r0 = mw + (lane >> 2);
        const int nc = (lane & 3) * 2;
        #pragma unroll
        for (int nf = 0; nf < NF; ++nf) {
            *(float2*)&Dst[r0 * PD + nw + nf * 8 + nc]       = make_float2(acc[nf][0], acc[nf][1]);
            *(float2*)&Dst[(r0 + 8) * PD + nw + nf * 8 + nc] = make_float2(acc[nf][2], acc[nf][3]);
        }
    }
    __syncthreads();
    if constexpr (DIM == 1) {
        const int nr = (batch - z_lo < MROWS) ? (batch - z_lo) : MROWS;
        constexpr int Q = MUL / 4;                // 32 float4s per row
        for (int idx = tid; idx < nr * Q; idx += 256) {
            const int r = idx / Q;
            const int q = idx & (Q - 1);
            *(float4*)&out[(long)(z_lo + r) * 592 + OFF + q * 4] =
                *(const float4*)&Dst[r * PD + q * 4];
        }
    } else {
        constexpr int ZST2 = 256 / MUL;
        const int n     = tid & (MUL - 1);
        const int zoff2 = tid / MUL;
        for (int zz = zoff2; zz < n_rows; zz += ZST2) {
            float* orow = out + (long)(z_lo + zz) * 592 + OFF + n * DIM;
            const int mlb = mbase + zz * DIM;
            #pragma unroll
            for (int i = 0; i < DIM; ++i) {
                const int ml = mlb + i;
                if (ml >= 0 && ml < MROWS) orow[i] = Dst[ml * PD + n];
            }
        }
    }
}

__global__ void __launch_bounds__(256) fused_irrep_kernel(
    const float* __restrict__ x, float* __restrict__ out, int batch,
    int nb0, int nb01, int nb012)
{
    extern __shared__ char smem[];
    const int b = blockIdx.x;
    if (b < nb0) {
        irrep_gemm<128, 1, 0, 0, 64>(x, out, batch, b, smem);
    } else if (b < nb01) {
        irrep_gemm<64, 3, 128, 20480, 128>(x, out, batch, b - nb0, smem);
    } else if (b < nb012) {
        irrep_gemm<32, 5, 320, 25600, 128>(x, out, batch, b - nb01, smem);
    } else {
        irrep_gemm<16, 7, 480, 26880, 128>(x, out, batch, b - nb012, smem);
    }
}

extern "C" void kernel_launch(void* const* d_in, const int* in_sizes, int n_in,
                              void* d_out, int out_size)
{
    const float* x = (const float*)d_in[0];
    const float* w = (const float*)d_in[1];
    float* out = (float*)d_out;
    const int batch = in_sizes[0] / 592;

    w_prep_kernel<<<(21760 + 255) / 256, 256>>>(w);

    const int nb0 = (batch + 63) / 64;
    const int nb1 = (batch * 3 + 127) / 128;
    const int nb2 = (batch * 5 + 127) / 128;
    const int nb3 = (batch * 7 + 127) / 128;
    const int total = nb0 + nb1 + nb2 + nb3;

    const size_t smem = 36864;   // max(staging 30720, Dstage 36864 for block1)
    cudaFuncSetAttribute(fused_irrep_kernel,
                         cudaFuncAttributeMaxDynamicSharedMemorySize, (int)smem);
    fused_irrep_kernel<<<total, 256, smem>>>(x, out, batch,
                                             nb0, nb0 + nb1, nb0 + nb1 + nb2);
}

// round 5
// speedup vs baseline: 1.9012x; 1.0078x over previous
#include <cuda_runtime.h>
#include <cuda_bf16.h>
#include <cstdint>

// ============================================================================
// Block-diagonal irrep linear, fused HMMA bf16 3-term split kernel.
// Per block: D[m,n] = sum_k A[m,k]*W[k,n]*pw, m = z*DIM+i.
// W pre-split (hi/lo bf16, pw folded, padded smem layout) by a prep kernel.
// ============================================================================

__device__ __forceinline__ uint32_t smem_u32(const void* p) {
    uint32_t a;
    asm("{ .reg .u64 t; cvta.to.shared.u64 t, %1; cvt.u32.u64 %0, t; }" : "=r"(a) : "l"(p));
    return a;
}
__device__ __forceinline__ void ldsm4(uint32_t* r, uint32_t addr) {
    asm volatile("ldmatrix.sync.aligned.m8n8.x4.shared.b16 {%0,%1,%2,%3}, [%4];"
                 : "=r"(r[0]), "=r"(r[1]), "=r"(r[2]), "=r"(r[3]) : "r"(addr));
}
__device__ __forceinline__ void mma16816(float* c, const uint32_t* a, const uint32_t* b) {
    asm volatile("mma.sync.aligned.m16n8k16.row.col.f32.bf16.bf16.f32 "
                 "{%0,%1,%2,%3}, {%4,%5,%6,%7}, {%8,%9}, {%0,%1,%2,%3};"
                 : "+f"(c[0]), "+f"(c[1]), "+f"(c[2]), "+f"(c[3])
                 : "r"(a[0]), "r"(a[1]), "r"(a[2]), "r"(a[3]), "r"(b[0]), "r"(b[1]));
}
__device__ __forceinline__ void split_bf16(float v, __nv_bfloat16& h, __nv_bfloat16& l) {
    h = __float2bfloat16(v);
    l = __float2bfloat16(v - __bfloat162float(h));
}
__device__ __forceinline__ uint32_t pack2(__nv_bfloat16 a, __nv_bfloat16 b) {
    return ((uint32_t)__bfloat16_as_ushort(b) << 16) | __bfloat16_as_ushort(a);
}

// ---- W images: per block, per K-chunk, [n][kl] with padded stride PB=KC+8 ----
// halves offsets: b0=0 (4 chunks x 128x40), b1=20480 (2 x 64x40),
//                 b2=25600 (32x40), b3=26880 (16x24); total 27264
__device__ __align__(16) __nv_bfloat16 g_bh[27264];
__device__ __align__(16) __nv_bfloat16 g_bl[27264];

__global__ void w_prep_kernel(const float* __restrict__ w) {
    int t = blockIdx.x * 256 + threadIdx.x;
    if (t >= 21760) return;
    int dst; float pw;
    if (t < 16384) {                  // block0: MUL=128, KC=32
        int u = t >> 7, n = t & 127;
        dst = ((u >> 5) * 5120) + n * 40 + (u & 31);
        pw = 0.08838834764831845f;
    } else if (t < 20480) {           // block1: MUL=64, KC=32
        int local = t - 16384;
        int u = local >> 6, n = local & 63;
        dst = 20480 + ((u >> 5) * 2560) + n * 40 + (u & 31);
        pw = 0.125f;
    } else if (t < 21504) {           // block2: MUL=32, KC=32
        int local = t - 20480;
        int u = local >> 5, n = local & 31;
        dst = 25600 + n * 40 + u;
        pw = 0.17677669529663687f;
    } else {                          // block3: MUL=16, KC=16
        int local = t - 21504;
        int u = local >> 4, n = local & 15;
        dst = 26880 + n * 24 + u;
        pw = 0.25f;
    }
    float val = w[t] * pw;
    __nv_bfloat16 h, l;
    split_bf16(val, h, l);
    g_bh[dst] = h;
    g_bl[dst] = l;
}

// ---- per-block GEMM body ----
template <int MUL, int DIM, int OFF, int IMG, int MROWS>
__device__ __forceinline__ void irrep_gemm(
    const float* __restrict__ x, float* __restrict__ out,
    int batch, int cta, char* smem)
{
    constexpr int KC  = (MUL < 32) ? MUL : 32;   // K per chunk (pow2)
    constexpr int NCH = MUL / KC;
    constexpr int KS  = KC / 16;
    constexpr int PA  = KC + 8;                   // padded strides (halves)
    constexpr int PB  = KC + 8;
    constexpr int WN  = (MROWS == 64) ? 2 : 1;    // n-warp split (block0 only)
    constexpr int NPW = MUL / WN;                 // n per warp
    constexpr int NF  = NPW / 8;
    constexpr int PD  = MUL + 8;                  // Dstage stride (floats)

    __nv_bfloat16* Ah = (__nv_bfloat16*)smem;
    __nv_bfloat16* Al = Ah + MROWS * PA;
    __nv_bfloat16* Bh = Al + MROWS * PA;
    __nv_bfloat16* Bl = Bh + MUL * PB;
    float* Dst = (float*)smem;                    // epilogue alias

    const int tid  = threadIdx.x;
    const int lane = tid & 31;
    const int wid  = tid >> 5;
    const int m0   = cta * MROWS;
    const int mw   = (wid & (MROWS / 16 - 1)) * 16;
    const int nw   = (WN == 2) ? (wid >> 2) * NPW : 0;

    const int z_lo = m0 / DIM;
    int z_hi = (m0 + MROWS - 1) / DIM;
    if (z_hi > batch - 1) z_hi = batch - 1;
    const int n_rows = z_hi - z_lo + 1;
    const int mbase = z_lo * DIM - m0;            // in (-DIM, 0]

    const uint32_t sAh = smem_u32(Ah), sAl = smem_u32(Al);
    const uint32_t sBh = smem_u32(Bh), sBl = smem_u32(Bl);
    const uint32_t aoff = (uint32_t)(((mw + (lane & 15)) * PA + ((lane >> 4) & 1) * 8) * 2);
    const uint32_t boff = (uint32_t)(((nw + (lane & 7) + ((lane >> 4) & 1) * 8) * PB
                                      + ((lane >> 3) & 1) * 8) * 2);

    float acc[NF][4];
    #pragma unroll
    for (int f = 0; f < NF; ++f)
        #pragma unroll
        for (int j = 0; j < 4; ++j) acc[f][j] = 0.0f;

    for (int c = 0; c < NCH; ++c) {
        if (c) __syncthreads();

        // ---- stage B chunk: plain uint4 copies of prepped images ----
        {
            const uint4* gh = (const uint4*)(g_bh + IMG + c * MUL * PB);
            const uint4* gl = (const uint4*)(g_bl + IMG + c * MUL * PB);
            uint4* dh = (uint4*)Bh;
            uint4* dl = (uint4*)Bl;
            constexpr int CNT = MUL * PB / 8;
            for (int i = tid; i < CNT; i += 256) { dh[i] = gh[i]; dl[i] = gl[i]; }
        }

        // ---- stage A chunk ----
        const int c0 = OFF + c * KC * DIM;
        if constexpr (DIM == 1) {
            const int nr = (batch - z_lo < MROWS) ? (batch - z_lo) : MROWS;
            constexpr int Q = KC / 4;             // float4s per row (pow2)
            for (int idx = tid; idx < nr * Q; idx += 256) {
                const int r = idx / Q;
                const int q = idx & (Q - 1);
                const float4 v = *(const float4*)(x + (long)(z_lo + r) * 592 + c0 + q * 4);
                __nv_bfloat16 h0, l0, h1, l1, h2, l2, h3, l3;
                split_bf16(v.x, h0, l0); split_bf16(v.y, h1, l1);
                split_bf16(v.z, h2, l2); split_bf16(v.w, h3, l3);
                uint2 ph = make_uint2(pack2(h0, h1), pack2(h2, h3));
                uint2 pl = make_uint2(pack2(l0, l1), pack2(l2, l3));
                *(uint2*)&Ah[r * PA + q * 4] = ph;
                *(uint2*)&Al[r * PA + q * 4] = pl;
            }
        } else {
            constexpr int KC2 = KC / 2;           // u-pairs per row (pow2)
            constexpr int ZST = 256 / KC2;
            const int up   = (tid & (KC2 - 1)) * 2;
            const int zoff = tid / KC2;
            for (int zz = zoff; zz < n_rows; zz += ZST) {
                const float* base = x + (long)(z_lo + zz) * 592 + c0 + up * DIM;
                const int mlb = mbase + zz * DIM;
                #pragma unroll
                for (int i = 0; i < DIM; ++i) {
                    const int ml = mlb + i;
                    if (ml >= 0 && ml < MROWS) {
                        const float v0 = base[i];
                        const float v1 = base[i + DIM];
                        __nv_bfloat16 h0, l0, h1, l1;
                        split_bf16(v0, h0, l0); split_bf16(v1, h1, l1);
                        *(uint32_t*)&Ah[ml * PA + up] = pack2(h0, h1);
                        *(uint32_t*)&Al[ml * PA + up] = pack2(l0, l1);
                    }
                }
            }
        }
        __syncthreads();

        // ---- MMA: 3-term split ----
        #pragma unroll
        for (int ks = 0; ks < KS; ++ks) {
            uint32_t ah[4], al[4];
            ldsm4(ah, sAh + aoff + ks * 32);
            ldsm4(al, sAl + aoff + ks * 32);
            #pragma unroll
            for (int nf2 = 0; nf2 < NF / 2; ++nf2) {
                uint32_t bh[4], bl[4];
                const uint32_t bo = boff + (uint32_t)(nf2 * 16 * PB * 2) + ks * 32;
                ldsm4(bh, sBh + bo);
                ldsm4(bl, sBl + bo);
                mma16816(acc[2 * nf2],     ah, bh);
                mma16816(acc[2 * nf2 + 1], ah, bh + 2);
                mma16816(acc[2 * nf2],     ah, bl);
                mma16816(acc[2 * nf2 + 1], ah, bl + 2);
                mma16816(acc[2 * nf2],     al, bh);
                mma16816(acc[2 * nf2 + 1], al, bh + 2);
            }
        }
    }

    // ---- epilogue: regs -> Dstage -> coalesced gmem (pw already folded) ----
    __syncthreads();
    {
        const int r0 = mw + (lane >> 2);
        const int nc = (lane & 3) * 2;
        #pragma unroll
        for (int nf = 0; nf < NF; ++nf) {
            *(float2*)&Dst[r0 * PD + nw + nf * 8 + nc]       = make_float2(acc[nf][0], acc[nf][1]);
            *(float2*)&Dst[(r0 + 8) * PD + nw + nf * 8 + nc] = make_float2(acc[nf][2], acc[nf][3]);
        }
    }
    __syncthreads();
    if constexpr (DIM == 1) {
        const int nr = (batch - z_lo < MROWS) ? (batch - z_lo) : MROWS;
        constexpr int Q = MUL / 4;                // 32 float4s per row
        for (int idx = tid; idx < nr * Q; idx += 256) {
            const int r = idx / Q;
            const int q = idx & (Q - 1);
            *(float4*)&out[(long)(z_lo + r) * 592 + OFF + q * 4] =
                *(const float4*)&Dst[r * PD + q * 4];
        }
    } else {
        constexpr int ZST2 = 256 / MUL;
        const int n     = tid & (MUL - 1);
        const int zoff2 = tid / MUL;
        for (int zz = zoff2; zz < n_rows; zz += ZST2) {
            float* orow = out + (long)(z_lo + zz) * 592 + OFF + n * DIM;
            const int mlb = mbase + zz * DIM;
            #pragma unroll
            for (int i = 0; i < DIM; ++i) {
                const int ml = mlb + i;
                if (ml >= 0 && ml < MROWS) orow[i] = Dst[ml * PD + n];
            }
        }
    }
}

__global__ void __launch_bounds__(256) fused_irrep_kernel(
    const float* __restrict__ x, float* __restrict__ out, int batch,
    int nb0, int nb01, int nb012)
{
    extern __shared__ char smem[];
    const int b = blockIdx.x;
    if (b < nb0) {
        irrep_gemm<128, 1, 0, 0, 64>(x, out, batch, b, smem);
    } else if (b < nb01) {
        irrep_gemm<64, 3, 128, 20480, 128>(x, out, batch, b - nb0, smem);
    } else if (b < nb012) {
        irrep_gemm<32, 5, 320, 25600, 128>(x, out, batch, b - nb01, smem);
    } else {
        irrep_gemm<16, 7, 480, 26880, 128>(x, out, batch, b - nb012, smem);
    }
}

extern "C" void kernel_launch(void* const* d_in, const int* in_sizes, int n_in,
                              void* d_out, int out_size)
{
    const float* x = (const float*)d_in[0];
    const float* w = (const float*)d_in[1];
    float* out = (float*)d_out;
    const int batch = in_sizes[0] / 592;

    w_prep_kernel<<<(21760 + 255) / 256, 256>>>(w);

    const int nb0 = (batch + 63) / 64;
    const int nb1 = (batch * 3 + 127) / 128;
    const int nb2 = (batch * 5 + 127) / 128;
    const int nb3 = (batch * 7 + 127) / 128;
    const int total = nb0 + nb1 + nb2 + nb3;

    const size_t smem = 36864;   // max(staging 30720, Dstage 36864 for block1)
    cudaFuncSetAttribute(fused_irrep_kernel,
                         cudaFuncAttributeMaxDynamicSharedMemorySize, (int)smem);
    fused_irrep_kernel<<<total, 256, smem>>>(x, out, batch,
                                             nb0, nb0 + nb1, nb0 + nb1 + nb2);
}

// round 7
// speedup vs baseline: 2.2484x; 1.1826x over previous
#include <cuda_runtime.h>
#include <cuda_bf16.h>
#include <cstdint>

// ============================================================================
// Block-diagonal irrep linear, fused HMMA bf16 3-term split kernel.
// R6: occupancy 4 CTAs/SM, block0 direct epilogue + chunk prefetch,
//     float2 staging for DIM>1, block3 MITER=2 (MROWS=256).
// ============================================================================

__device__ __forceinline__ uint32_t smem_u32(const void* p) {
    uint32_t a;
    asm("{ .reg .u64 t; cvta.to.shared.u64 t, %1; cvt.u32.u64 %0, t; }" : "=r"(a) : "l"(p));
    return a;
}
__device__ __forceinline__ void ldsm4(uint32_t* r, uint32_t addr) {
    asm volatile("ldmatrix.sync.aligned.m8n8.x4.shared.b16 {%0,%1,%2,%3}, [%4];"
                 : "=r"(r[0]), "=r"(r[1]), "=r"(r[2]), "=r"(r[3]) : "r"(addr));
}
__device__ __forceinline__ void mma16816(float* c, const uint32_t* a, const uint32_t* b) {
    asm volatile("mma.sync.aligned.m16n8k16.row.col.f32.bf16.bf16.f32 "
                 "{%0,%1,%2,%3}, {%4,%5,%6,%7}, {%8,%9}, {%0,%1,%2,%3};"
                 : "+f"(c[0]), "+f"(c[1]), "+f"(c[2]), "+f"(c[3])
                 : "r"(a[0]), "r"(a[1]), "r"(a[2]), "r"(a[3]), "r"(b[0]), "r"(b[1]));
}
__device__ __forceinline__ void split_bf16(float v, __nv_bfloat16& h, __nv_bfloat16& l) {
    h = __float2bfloat16(v);
    l = __float2bfloat16(v - __bfloat162float(h));
}
__device__ __forceinline__ uint32_t pack2(__nv_bfloat16 a, __nv_bfloat16 b) {
    return ((uint32_t)__bfloat16_as_ushort(b) << 16) | __bfloat16_as_ushort(a);
}

// ---- W images: per block, per K-chunk, [n][kl], padded stride PB=KC+8 ----
// halves offsets: b0=0 (4 x 128x40), b1=20480 (2 x 64x40), b2=25600 (32x40),
// b3=26880 (16x24); total 27264
__device__ __align__(16) __nv_bfloat16 g_bh[27264];
__device__ __align__(16) __nv_bfloat16 g_bl[27264];

__global__ void w_prep_kernel(const float* __restrict__ w) {
    int t = blockIdx.x * 256 + threadIdx.x;
    if (t >= 21760) return;
    int dst; float pw;
    if (t < 16384) {                  // block0: MUL=128, KC=32
        int u = t >> 7, n = t & 127;
        dst = ((u >> 5) * 5120) + n * 40 + (u & 31);
        pw = 0.08838834764831845f;
    } else if (t < 20480) {           // block1: MUL=64, KC=32
        int local = t - 16384;
        int u = local >> 6, n = local & 63;
        dst = 20480 + ((u >> 5) * 2560) + n * 40 + (u & 31);
        pw = 0.125f;
    } else if (t < 21504) {           // block2: MUL=32, KC=32
        int local = t - 20480;
        int u = local >> 5, n = local & 31;
        dst = 25600 + n * 40 + u;
        pw = 0.17677669529663687f;
    } else {                          // block3: MUL=16, KC=16
        int local = t - 21504;
        int u = local >> 4, n = local & 15;
        dst = 26880 + n * 24 + u;
        pw = 0.25f;
    }
    float val = w[t] * pw;
    __nv_bfloat16 h, l;
    split_bf16(val, h, l);
    g_bh[dst] = h;
    g_bl[dst] = l;
}

// ---- per-block GEMM body ----
template <int MUL, int DIM, int OFF, int IMG, int WM, int WN, int MITER>
__device__ __forceinline__ void irrep_gemm(
    const float* __restrict__ x, float* __restrict__ out,
    int batch, int cta, char* smem)
{
    constexpr int KC    = (MUL < 32) ? MUL : 32;
    constexpr int NCH   = MUL / KC;
    constexpr int KS    = KC / 16;
    constexpr int PA    = KC + 8;
    constexpr int PB    = KC + 8;
    constexpr int NPW   = MUL / WN;
    constexpr int NF    = NPW / 8;
    constexpr int MROWS = WM * MITER * 16;
    constexpr int ENC   = (MUL < 32) ? MUL : 32;       // epilogue n-chunk
    constexpr int PD    = (MUL == 16) ? 28 : 40;       // Dstage stride (floats)

    __nv_bfloat16* Ah = (__nv_bfloat16*)smem;
    __nv_bfloat16* Al = Ah + MROWS * PA;
    __nv_bfloat16* Bh = Al + MROWS * PA;
    __nv_bfloat16* Bl = Bh + MUL * PB;
    float* Dst = (float*)smem;                         // epilogue alias

    const int tid  = threadIdx.x;
    const int lane = tid & 31;
    const int wid  = tid >> 5;
    const int m0   = cta * MROWS;
    const int mw   = (wid & (WM - 1)) * 16;
    const int nw   = (WN == 2) ? (wid >> 2) * NPW : 0;

    const int z_lo = m0 / DIM;
    int z_hi = (m0 + MROWS - 1) / DIM;
    if (z_hi > batch - 1) z_hi = batch - 1;
    const int n_rows = z_hi - z_lo + 1;
    const int mbase  = z_lo * DIM - m0;                // in (-DIM, 0]

    const uint32_t sAh = smem_u32(Ah), sAl = smem_u32(Al);
    const uint32_t sBh = smem_u32(Bh), sBl = smem_u32(Bl);
    uint32_t aoff[MITER];
    #pragma unroll
    for (int mi = 0; mi < MITER; ++mi)
        aoff[mi] = (uint32_t)(((mi * WM * 16 + mw + (lane & 15)) * PA
                               + ((lane >> 4) & 1) * 8) * 2);
    const uint32_t boff = (uint32_t)(((nw + (lane & 7) + ((lane >> 4) & 1) * 8) * PB
                                      + ((lane >> 3) & 1) * 8) * 2);

    float acc[MITER][NF][4];
    #pragma unroll
    for (int mi = 0; mi < MITER; ++mi)
        #pragma unroll
        for (int f = 0; f < NF; ++f)
            #pragma unroll
            for (int j = 0; j < 4; ++j) acc[mi][f][j] = 0.0f;

    const int nr = (batch - z_lo < MROWS) ? (batch - z_lo) : MROWS;  // DIM==1 rows
    constexpr int Q = KC / 4;                                        // float4/row

    float4 pre[2];
    auto load_chunk = [&](int c) {
        const int c0_ = OFF + c * KC;
        #pragma unroll
        for (int t = 0; t < 2; ++t) {
            const int idx = tid + t * 256;
            if (idx < nr * Q)
                pre[t] = *(const float4*)(x + (long)(z_lo + (idx >> 3)) * 592
                                          + c0_ + (idx & 7) * 4);
        }
    };
    auto store_chunk = [&]() {
        #pragma unroll
        for (int t = 0; t < 2; ++t) {
            const int idx = tid + t * 256;
            if (idx < nr * Q) {
                const float4 v = pre[t];
                __nv_bfloat16 h0, l0, h1, l1, h2, l2, h3, l3;
                split_bf16(v.x, h0, l0); split_bf16(v.y, h1, l1);
                split_bf16(v.z, h2, l2); split_bf16(v.w, h3, l3);
                const int r = idx >> 3, q = idx & 7;
                *(uint2*)&Ah[r * PA + q * 4] = make_uint2(pack2(h0, h1), pack2(h2, h3));
                *(uint2*)&Al[r * PA + q * 4] = make_uint2(pack2(l0, l1), pack2(l2, l3));
            }
        }
    };
    auto copy_b = [&](int c) {
        const uint4* gh = (const uint4*)(g_bh + IMG + c * MUL * PB);
        const uint4* gl = (const uint4*)(g_bl + IMG + c * MUL * PB);
        uint4* dh = (uint4*)Bh;
        uint4* dl = (uint4*)Bl;
        constexpr int CNT = MUL * PB / 8;
        for (int i = tid; i < CNT; i += 256) { dh[i] = gh[i]; dl[i] = gl[i]; }
    };
    auto mma_chunk = [&]() {
        #pragma unroll
        for (int ks = 0; ks < KS; ++ks) {
            uint32_t ah[MITER][4], al[MITER][4];
            #pragma unroll
            for (int mi = 0; mi < MITER; ++mi) {
                ldsm4(ah[mi], sAh + aoff[mi] + ks * 32);
                ldsm4(al[mi], sAl + aoff[mi] + ks * 32);
            }
            #pragma unroll
            for (int nf2 = 0; nf2 < NF / 2; ++nf2) {
                uint32_t bh[4], bl[4];
                const uint32_t bo = boff + (uint32_t)(nf2 * 16 * PB * 2) + ks * 32;
                ldsm4(bh, sBh + bo);
                ldsm4(bl, sBl + bo);
                #pragma unroll
                for (int mi = 0; mi < MITER; ++mi) {
                    mma16816(acc[mi][2 * nf2],     ah[mi], bh);
                    mma16816(acc[mi][2 * nf2 + 1], ah[mi], bh + 2);
                    mma16816(acc[mi][2 * nf2],     ah[mi], bl);
                    mma16816(acc[mi][2 * nf2 + 1], ah[mi], bl + 2);
                    mma16816(acc[mi][2 * nf2],     al[mi], bh);
                    mma16816(acc[mi][2 * nf2 + 1], al[mi], bh + 2);
                }
            }
        }
    };

    if constexpr (DIM == 1) {
        load_chunk(0);
        for (int c = 0; c < NCH; ++c) {
            __syncthreads();
            copy_b(c);
            store_chunk();
            __syncthreads();
            if (c + 1 < NCH) load_chunk(c + 1);
            mma_chunk();
        }
    } else {
        constexpr int KC2 = KC / 2;
        constexpr int ZST = 256 / KC2;
        const int up   = (tid & (KC2 - 1)) * 2;
        const int zoff = tid / KC2;
        for (int c = 0; c < NCH; ++c) {
            if (c) __syncthreads();
            copy_b(c);
            const int c0 = OFF + c * KC * DIM;
            for (int zz = zoff; zz < n_rows; zz += ZST) {
                const float2* bp = (const float2*)(x + (long)(z_lo + zz) * 592
                                                   + c0 + up * DIM);
                float r[2 * DIM];
                #pragma unroll
                for (int t = 0; t < DIM; ++t) {
                    const float2 v = bp[t];
                    r[2 * t] = v.x; r[2 * t + 1] = v.y;
                }
                const int mlb = mbase + zz * DIM;
                #pragma unroll
                for (int i = 0; i < DIM; ++i) {
                    const int ml = mlb + i;
                    if (ml >= 0 && ml < MROWS) {
                        __nv_bfloat16 h0, l0, h1, l1;
                        split_bf16(r[i], h0, l0);
                        split_bf16(r[i + DIM], h1, l1);
                        *(uint32_t*)&Ah[ml * PA + up] = pack2(h0, h1);
                        *(uint32_t*)&Al[ml * PA + up] = pack2(l0, l1);
                    }
                }
            }
            __syncthreads();
            mma_chunk();
        }
    }

    // ---- epilogue ----
    if constexpr (DIM == 1) {
        // direct register -> gmem (rows are batch indices; cols 32B-aligned)
        const int r0 = mw + (lane >> 2);
        const int nc = (lane & 3) * 2;
        #pragma unroll
        for (int h = 0; h < 2; ++h) {
            const int z = z_lo + r0 + h * 8;
            if (z < batch) {
                float* orow = out + (long)z * 592 + OFF + nw + nc;
                #pragma unroll
                for (int nf = 0; nf < NF; ++nf)
                    *(float2*)(orow + nf * 8) =
                        make_float2(acc[0][nf][2 * h], acc[0][nf][2 * h + 1]);
            }
        }
    } else {
        const int r0 = mw + (lane >> 2);
        const int nc = (lane & 3) * 2;
        constexpr int ZSTE = 256 / ENC;
        const int n2   = tid & (ENC - 1);
        const int zoffe = tid / ENC;
        #pragma unroll
        for (int e0 = 0; e0 < MUL; e0 += ENC) {
            __syncthreads();
            #pragma unroll
            for (int mi = 0; mi < MITER; ++mi) {
                const int rb = mi * WM * 16 + r0;
                #pragma unroll
                for (int nf = e0 / 8; nf < (e0 + ENC) / 8; ++nf) {
                    const int col = nf * 8 - e0 + nc;
                    *(float2*)&Dst[rb * PD + col] =
                        make_float2(acc[mi][nf][0], acc[mi][nf][1]);
                    *(float2*)&Dst[(rb + 8) * PD + col] =
                        make_float2(acc[mi][nf][2], acc[mi][nf][3]);
                }
            }
            __syncthreads();
            const int n = e0 + n2;
            for (int zz = zoffe; zz < n_rows; zz += ZSTE) {
                float* orow = out + (long)(z_lo + zz) * 592 + OFF + n * DIM;
                const int mlb = mbase + zz * DIM;
                #pragma unroll
                for (int i = 0; i < DIM; ++i) {
                    const int ml = mlb + i;
                    if (ml >= 0 && ml < MROWS) orow[i] = Dst[ml * PD + n2];
                }
            }
        }
    }
}

__global__ void __launch_bounds__(256, 4) fused_irrep_kernel(
    const float* __restrict__ x, float* __restrict__ out, int batch,
    int nb0, int nb01, int nb012)
{
    extern __shared__ char smem[];
    const int b = blockIdx.x;
    if (b < nb0) {
        irrep_gemm<128, 1, 0, 0, 4, 2, 1>(x, out, batch, b, smem);
    } else if (b < nb01) {
        irrep_gemm<64, 3, 128, 20480, 8, 1, 1>(x, out, batch, b - nb0, smem);
    } else if (b < nb012) {
        irrep_gemm<32, 5, 320, 25600, 8, 1, 1>(x, out, batch, b - nb01, smem);
    } else {
        irrep_gemm<16, 7, 480, 26880, 8, 1, 2>(x, out, batch, b - nb012, smem);
    }
}

extern "C" void kernel_launch(void* const* d_in, const int* in_sizes, int n_in,
                              void* d_out, int out_size)
{
    const float* x = (const float*)d_in[0];
    const float* w = (const float*)d_in[1];
    float* out = (float*)d_out;
    const int batch = in_sizes[0] / 592;

    w_prep_kernel<<<(21760 + 255) / 256, 256>>>(w);

    const int nb0 = (batch + 63) / 64;          // MROWS 64
    const int nb1 = (batch * 3 + 127) / 128;    // MROWS 128
    const int nb2 = (batch * 5 + 127) / 128;    // MROWS 128
    const int nb3 = (batch * 7 + 255) / 256;    // MROWS 256
    const int total = nb0 + nb1 + nb2 + nb3;

    const size_t smem = 30720;
    cudaFuncSetAttribute(fused_irrep_kernel,
                         cudaFuncAttributeMaxDynamicSharedMemorySize, (int)smem);
    fused_irrep_kernel<<<total, 256, smem>>>(x, out, batch,
                                             nb0, nb0 + nb1, nb0 + nb1 + nb2);
}